// round 3
// baseline (speedup 1.0000x reference)
#include <cuda_runtime.h>

// Problem constants
#define BSZ   4
#define CSQ   1024
#define PSQ   1024
#define DIN   1024
#define NH    16
#define HDIM  64
#define TT    2048        // T = CS + PS
#define LQG   4096        // BSZ*CSQ global query rows
#define HD    1024        // NH*HDIM
#define SCALE 0.125f      // 1/sqrt(64)

// ---------------------------------------------------------------------------
// Scratch (device globals; no dynamic allocation allowed)
// ---------------------------------------------------------------------------
__device__ float g_q [(size_t)LQG * HD];                 //  16.8 MB  q_tfmd
__device__ float g_kv[(size_t)BSZ * TT * 2 * HD];        //  67 MB    [k | v]
__device__ float g_p [(size_t)TT * HD];                  //   8.4 MB  p_tfmd
__device__ float g_P [(size_t)NH * LQG * TT];            // 512 MB    (q+v)@p^T per head
__device__ float g_S [(size_t)BSZ * NH * CSQ * TT];      // 512 MB    attention scores
__device__ float g_ao[(size_t)LQG * HD];                 //  16.8 MB  attn output (pre W_out)

// ---------------------------------------------------------------------------
// Generic 128x128x8 SGEMM, row-major A(MxK) * B(KxN) -> C(MxN).
// MODE 0: A is plain.  MODE 1: A rows are the virtual concat(memory, input_)
// along the sequence axis (row L -> b=L/T, r=L%T; r<PS: memory else input).
// 256 threads, 8x8 per thread. Requires M%128==0, N%128==0, K%8==0.
// ---------------------------------------------------------------------------
template <int MODE>
__global__ void __launch_bounds__(256) sgemm128(
    const float* __restrict__ A, const float* __restrict__ A2,
    const float* __restrict__ B, float* __restrict__ C,
    int M, int N, int K)
{
    __shared__ float As[8][132];   // transposed A tile, padded vs bank conflicts
    __shared__ float Bs[8][128];

    const int tid = threadIdx.x;
    const int bm  = blockIdx.y * 128;
    const int bn  = blockIdx.x * 128;
    const int tx  = tid & 15;
    const int ty  = tid >> 4;

    // A tile load mapping: 128 rows x 8 cols, one float4 per thread
    const int a_r = tid >> 1;
    const int a_c = (tid & 1) << 2;
    const float* arow;
    if (MODE == 0) {
        arow = A + (size_t)(bm + a_r) * K;
    } else {
        int row = bm + a_r;
        int b   = row / TT;
        int r   = row - b * TT;
        if (r < PSQ) arow = A  + (size_t)(b * PSQ + r)          * K;
        else         arow = A2 + (size_t)(b * CSQ + (r - PSQ))  * K;
    }
    // B tile load mapping: 8 rows x 128 cols
    const int b_r = tid >> 5;
    const int b_c = (tid & 31) << 2;
    const float* bp = B + (size_t)b_r * N + bn + b_c;

    float acc[8][8] = {};

    for (int k0 = 0; k0 < K; k0 += 8) {
        float4 av = *(const float4*)(arow + k0 + a_c);
        float4 bv = *(const float4*)(bp + (size_t)k0 * N);
        As[a_c + 0][a_r] = av.x;
        As[a_c + 1][a_r] = av.y;
        As[a_c + 2][a_r] = av.z;
        As[a_c + 3][a_r] = av.w;
        *(float4*)&Bs[b_r][b_c] = bv;
        __syncthreads();
#pragma unroll
        for (int k = 0; k < 8; k++) {
            float a[8], b[8];
            *(float4*)&a[0] = *(const float4*)&As[k][ty * 8];
            *(float4*)&a[4] = *(const float4*)&As[k][ty * 8 + 4];
            *(float4*)&b[0] = *(const float4*)&Bs[k][tx * 8];
            *(float4*)&b[4] = *(const float4*)&Bs[k][tx * 8 + 4];
#pragma unroll
            for (int i = 0; i < 8; i++)
#pragma unroll
                for (int j = 0; j < 8; j++)
                    acc[i][j] += a[i] * b[j];
        }
        __syncthreads();
    }
#pragma unroll
    for (int i = 0; i < 8; i++) {
        float* crow = C + (size_t)(bm + ty * 8 + i) * N + bn + tx * 8;
        *(float4*)(crow)     = make_float4(acc[i][0], acc[i][1], acc[i][2], acc[i][3]);
        *(float4*)(crow + 4) = make_float4(acc[i][4], acc[i][5], acc[i][6], acc[i][7]);
    }
}

// ---------------------------------------------------------------------------
// P[h][L][jj] = sum_d (q[L,h,d]+v[h,d]) * p[jj,h,d]
// Per-head NT GEMM: M=LQG(128-tile) x N=TT(64-tile) x K=64.
// ---------------------------------------------------------------------------
__global__ void __launch_bounds__(256) pos_gemm(
    const float* __restrict__ q, const float* __restrict__ p,
    const float* __restrict__ vb, float* __restrict__ P)
{
    __shared__ float As[16][132];
    __shared__ float Bs[16][68];
    const int tid = threadIdx.x;
    const int h   = blockIdx.z;
    const int L0  = blockIdx.y * 128;
    const int j0  = blockIdx.x * 64;
    const int tx  = tid & 15;
    const int ty  = tid >> 4;
    float acc[8][4] = {};

    for (int k0 = 0; k0 < HDIM; k0 += 16) {
#pragma unroll
        for (int rr = 0; rr < 2; rr++) {
            int t  = tid + rr * 256;
            int l  = t >> 2;
            int kq = (t & 3) << 2;
            float4 av = *(const float4*)(q  + (size_t)(L0 + l) * HD + h * HDIM + k0 + kq);
            float4 vv = *(const float4*)(vb + h * HDIM + k0 + kq);
            As[kq + 0][l] = av.x + vv.x;
            As[kq + 1][l] = av.y + vv.y;
            As[kq + 2][l] = av.z + vv.z;
            As[kq + 3][l] = av.w + vv.w;
        }
        {
            int n  = tid >> 2;
            int kq = (tid & 3) << 2;
            float4 bv = *(const float4*)(p + (size_t)(j0 + n) * HD + h * HDIM + k0 + kq);
            Bs[kq + 0][n] = bv.x;
            Bs[kq + 1][n] = bv.y;
            Bs[kq + 2][n] = bv.z;
            Bs[kq + 3][n] = bv.w;
        }
        __syncthreads();
#pragma unroll
        for (int k = 0; k < 16; k++) {
            float a[8], b[4];
            *(float4*)&a[0] = *(const float4*)&As[k][ty * 8];
            *(float4*)&a[4] = *(const float4*)&As[k][ty * 8 + 4];
            *(float4*)&b[0] = *(const float4*)&Bs[k][tx * 4];
#pragma unroll
            for (int i = 0; i < 8; i++)
#pragma unroll
                for (int j = 0; j < 4; j++)
                    acc[i][j] += a[i] * b[j];
        }
        __syncthreads();
    }
#pragma unroll
    for (int i = 0; i < 8; i++) {
        float* out = P + ((size_t)h * LQG + L0 + ty * 8 + i) * TT + j0 + tx * 4;
        *(float4*)out = make_float4(acc[i][0], acc[i][1], acc[i][2], acc[i][3]);
    }
}

// ---------------------------------------------------------------------------
// Scores: S[b,h,i,j] = (q[b,i,h,:]+u[h])·k[b,j,h,:] + rel_shift(P) gather,
// masked (j > i+PS -> -1e30). Per (b,h): M=CSQ(128) x N=TT(64) x K=64.
// rel-shift: L = b*CS+i; s = j + BS*CS - L; n = (s>T)+(s>2T+1);
//            j' = s - n*(T+1); pos = (j'==0) ? 0 : P[h][L+n][j'-1]
// ---------------------------------------------------------------------------
__global__ void __launch_bounds__(256) score_gemm(
    const float* __restrict__ q, const float* __restrict__ kv,
    const float* __restrict__ ub, const float* __restrict__ Pm,
    float* __restrict__ S)
{
    __shared__ float As[16][132];
    __shared__ float Bs[16][68];
    const int tid = threadIdx.x;
    const int bh  = blockIdx.z;
    const int b   = bh >> 4;
    const int h   = bh & 15;
    const int i0  = blockIdx.y * 128;
    const int j0  = blockIdx.x * 64;
    const int tx  = tid & 15;
    const int ty  = tid >> 4;
    float acc[8][4] = {};

    for (int k0 = 0; k0 < HDIM; k0 += 16) {
#pragma unroll
        for (int rr = 0; rr < 2; rr++) {
            int t  = tid + rr * 256;
            int l  = t >> 2;
            int kq = (t & 3) << 2;
            float4 av = *(const float4*)(q  + (size_t)(b * CSQ + i0 + l) * HD + h * HDIM + k0 + kq);
            float4 uu = *(const float4*)(ub + h * HDIM + k0 + kq);
            As[kq + 0][l] = av.x + uu.x;
            As[kq + 1][l] = av.y + uu.y;
            As[kq + 2][l] = av.z + uu.z;
            As[kq + 3][l] = av.w + uu.w;
        }
        {
            int n  = tid >> 2;
            int kq = (tid & 3) << 2;
            float4 bv = *(const float4*)(kv + ((size_t)b * TT + j0 + n) * (2 * HD) + h * HDIM + k0 + kq);
            Bs[kq + 0][n] = bv.x;
            Bs[kq + 1][n] = bv.y;
            Bs[kq + 2][n] = bv.z;
            Bs[kq + 3][n] = bv.w;
        }
        __syncthreads();
#pragma unroll
        for (int k = 0; k < 16; k++) {
            float a[8], bq[4];
            *(float4*)&a[0]  = *(const float4*)&As[k][ty * 8];
            *(float4*)&a[4]  = *(const float4*)&As[k][ty * 8 + 4];
            *(float4*)&bq[0] = *(const float4*)&Bs[k][tx * 4];
#pragma unroll
            for (int i = 0; i < 8; i++)
#pragma unroll
                for (int j = 0; j < 4; j++)
                    acc[i][j] += a[i] * bq[j];
        }
        __syncthreads();
    }

#pragma unroll
    for (int i = 0; i < 8; i++) {
        int ii = i0 + ty * 8 + i;
        int L  = b * CSQ + ii;
        float out4[4];
#pragma unroll
        for (int j = 0; j < 4; j++) {
            int jj = j0 + tx * 4 + j;
            float val;
            if (jj > ii + PSQ) {
                val = -1e30f;
            } else {
                int s  = jj + LQG - L;
                int n  = (s > TT) + (s > 2 * TT + 1);
                int jp = s - n * (TT + 1);
                int Lp = L + n;
                float pos = 0.f;
                if (jp > 0 && Lp < LQG)
                    pos = Pm[((size_t)h * LQG + Lp) * TT + (jp - 1)];
                val = acc[i][j] + pos;
            }
            out4[j] = val;
        }
        float* so = S + ((size_t)(b * NH + h) * CSQ + ii) * TT + j0 + tx * 4;
        *(float4*)so = make_float4(out4[0], out4[1], out4[2], out4[3]);
    }
}

// ---------------------------------------------------------------------------
// Row softmax over j (T=2048) of SCALE*score, in place. 1 block per row.
// ---------------------------------------------------------------------------
__global__ void __launch_bounds__(256) softmax_k(float* __restrict__ S)
{
    const int t = threadIdx.x;
    float* x = S + (size_t)blockIdx.x * TT;
    float v[8];
    float m = -3.0e38f;
#pragma unroll
    for (int r = 0; r < 8; r++) {
        v[r] = x[t + 256 * r];
        m = fmaxf(m, v[r]);
    }
#pragma unroll
    for (int o = 16; o > 0; o >>= 1)
        m = fmaxf(m, __shfl_xor_sync(0xffffffffu, m, o));
    __shared__ float red[8];
    if ((t & 31) == 0) red[t >> 5] = m;
    __syncthreads();
    float bm = red[0];
#pragma unroll
    for (int w = 1; w < 8; w++) bm = fmaxf(bm, red[w]);

    float s = 0.f;
#pragma unroll
    for (int r = 0; r < 8; r++) {
        v[r] = __expf((v[r] - bm) * SCALE);
        s += v[r];
    }
#pragma unroll
    for (int o = 16; o > 0; o >>= 1)
        s += __shfl_xor_sync(0xffffffffu, s, o);
    __syncthreads();
    if ((t & 31) == 0) red[t >> 5] = s;
    __syncthreads();
    float tot = 0.f;
#pragma unroll
    for (int w = 0; w < 8; w++) tot += red[w];
    float inv = 1.0f / tot;
#pragma unroll
    for (int r = 0; r < 8; r++)
        x[t + 256 * r] = v[r] * inv;
}

// ---------------------------------------------------------------------------
// ao[b,i,h,:] = sum_j S[b,h,i,j] * v[b,j,h,:]
// Per (b,h): M=CSQ(128-tile) x N=64 x K<=TT(16-step). K truncated by causality:
// rows [i0, i0+127] have zero prob for j >= i0+128+PS.
// ---------------------------------------------------------------------------
__global__ void __launch_bounds__(256) awv_gemm(
    const float* __restrict__ S, const float* __restrict__ kv,
    float* __restrict__ ao)
{
    __shared__ float As[16][132];
    __shared__ float Bs[16][68];
    const int tid = threadIdx.x;
    const int bh  = blockIdx.z;
    const int b   = bh >> 4;
    const int h   = bh & 15;
    const int i0  = blockIdx.y * 128;
    const int tx  = tid & 15;
    const int ty  = tid >> 4;
    float acc[8][4] = {};
    const int Kef = min(TT, i0 + 128 + PSQ);

    for (int k0 = 0; k0 < Kef; k0 += 16) {
#pragma unroll
        for (int rr = 0; rr < 2; rr++) {
            int t  = tid + rr * 256;
            int l  = t >> 2;
            int kq = (t & 3) << 2;
            float4 av = *(const float4*)(S + ((size_t)(b * NH + h) * CSQ + i0 + l) * TT + k0 + kq);
            As[kq + 0][l] = av.x;
            As[kq + 1][l] = av.y;
            As[kq + 2][l] = av.z;
            As[kq + 3][l] = av.w;
        }
        {
            int r  = tid >> 4;
            int dq = (tid & 15) << 2;
            float4 bv = *(const float4*)(kv + ((size_t)b * TT + k0 + r) * (2 * HD) + HD + h * HDIM + dq);
            *(float4*)&Bs[r][dq] = bv;
        }
        __syncthreads();
#pragma unroll
        for (int k = 0; k < 16; k++) {
            float a[8], bq[4];
            *(float4*)&a[0]  = *(const float4*)&As[k][ty * 8];
            *(float4*)&a[4]  = *(const float4*)&As[k][ty * 8 + 4];
            *(float4*)&bq[0] = *(const float4*)&Bs[k][tx * 4];
#pragma unroll
            for (int i = 0; i < 8; i++)
#pragma unroll
                for (int j = 0; j < 4; j++)
                    acc[i][j] += a[i] * bq[j];
        }
        __syncthreads();
    }
#pragma unroll
    for (int i = 0; i < 8; i++) {
        float* o = ao + ((size_t)b * CSQ + i0 + ty * 8 + i) * HD + h * HDIM + tx * 4;
        *(float4*)o = make_float4(acc[i][0], acc[i][1], acc[i][2], acc[i][3]);
    }
}

// ---------------------------------------------------------------------------
// Launch: 8 kernels, all default-stream (sequential deps), graph-capturable.
// Inputs (metadata order): input_, pos_embs, memory, u, v, W_kv, W_q, W_p,
// W_out, mask (mask is recomputed analytically; d_in[9] unused).
// ---------------------------------------------------------------------------
extern "C" void kernel_launch(void* const* d_in, const int* in_sizes, int n_in,
                              void* d_out, int out_size)
{
    const float* input_ = (const float*)d_in[0];
    const float* pos    = (const float*)d_in[1];
    const float* memory = (const float*)d_in[2];
    const float* u      = (const float*)d_in[3];
    const float* v      = (const float*)d_in[4];
    const float* W_kv   = (const float*)d_in[5];
    const float* W_q    = (const float*)d_in[6];
    const float* W_p    = (const float*)d_in[7];
    const float* W_out  = (const float*)d_in[8];
    float* out = (float*)d_out;

    float *qb, *kvb, *pb, *Pb, *Sb, *aob;
    cudaGetSymbolAddress((void**)&qb,  g_q);
    cudaGetSymbolAddress((void**)&kvb, g_kv);
    cudaGetSymbolAddress((void**)&pb,  g_p);
    cudaGetSymbolAddress((void**)&Pb,  g_P);
    cudaGetSymbolAddress((void**)&Sb,  g_S);
    cudaGetSymbolAddress((void**)&aob, g_ao);

    dim3 thr(256);

    // q = input_ @ W_q                      (4096 x 1024 x 1024)
    sgemm128<0><<<dim3(HD / 128, LQG / 128), thr>>>(input_, nullptr, W_q, qb, LQG, HD, DIN);
    // kv = concat(memory, input_) @ W_kv    (8192 x 1024 x 2048)
    sgemm128<1><<<dim3(2 * HD / 128, (BSZ * TT) / 128), thr>>>(memory, input_, W_kv, kvb, BSZ * TT, 2 * HD, DIN);
    // p = pos_embs @ W_p                    (2048 x 1024 x 1024)
    sgemm128<0><<<dim3(HD / 128, TT / 128), thr>>>(pos, nullptr, W_p, pb, TT, HD, DIN);
    // P[h] = (q + v) @ p^T per head         (16 x 4096 x 64 x 2048)
    pos_gemm<<<dim3(TT / 64, LQG / 128, NH), thr>>>(qb, pb, v, Pb);
    // scores + rel-shift gather + mask
    score_gemm<<<dim3(TT / 64, CSQ / 128, BSZ * NH), thr>>>(qb, kvb, u, Pb, Sb);
    // softmax
    softmax_k<<<BSZ * NH * CSQ, thr>>>(Sb);
    // attn @ V
    awv_gemm<<<dim3(1, CSQ / 128, BSZ * NH), thr>>>(Sb, kvb, aob);
    // out = ao @ W_out                      (4096 x 1024 x 1024)
    sgemm128<0><<<dim3(DIN / 128, LQG / 128), thr>>>(aob, nullptr, W_out, out, LQG, DIN, HD);
}

// round 4
// speedup vs baseline: 1.1973x; 1.1973x over previous
#include <cuda_runtime.h>

// Problem constants
#define BSZ   4
#define CSQ   1024
#define PSQ   1024
#define DIN   1024
#define NH    16
#define HDIM  64
#define TT    2048        // T = CS + PS
#define LQG   4096        // BSZ*CSQ global query rows
#define HD    1024        // NH*HDIM
#define SCALE 0.125f      // 1/sqrt(64)

// ---------------------------------------------------------------------------
// Scratch (device globals; no dynamic allocation allowed)
// ---------------------------------------------------------------------------
__device__ float g_q [(size_t)LQG * HD];                 //  16.8 MB  q_tfmd
__device__ float g_kv[(size_t)BSZ * TT * 2 * HD];        //  67 MB    [k | v]
__device__ float g_p [(size_t)TT * HD];                  //   8.4 MB  p_tfmd
__device__ float g_P [(size_t)NH * LQG * TT];            // 512 MB    (q+v)@p^T per head
__device__ float g_S [(size_t)BSZ * NH * CSQ * TT];      // 512 MB    attention scores
__device__ float g_ao[(size_t)LQG * HD];                 //  16.8 MB  attn output (pre W_out)

// ---------------------------------------------------------------------------
// tf32 helpers
// ---------------------------------------------------------------------------
__device__ __forceinline__ float tf32r(float x) {
    float y;
    asm("cvt.rna.tf32.f32 %0, %1;" : "=f"(y) : "f"(x));
    return y;
}

// D += A(16x8 row) * B(8x8 col)
__device__ __forceinline__ void mma8(float* d, const float* a, const float* b) {
    asm volatile(
        "mma.sync.aligned.m16n8k8.row.col.f32.tf32.tf32.f32 "
        "{%0,%1,%2,%3}, {%4,%5,%6,%7}, {%8,%9}, {%0,%1,%2,%3};"
        : "+f"(d[0]), "+f"(d[1]), "+f"(d[2]), "+f"(d[3])
        : "r"(__float_as_uint(a[0])), "r"(__float_as_uint(a[1])),
          "r"(__float_as_uint(a[2])), "r"(__float_as_uint(a[3])),
          "r"(__float_as_uint(b[0])), "r"(__float_as_uint(b[1])));
}

// Fragment loads from padded SMEM tiles: As/Bs row = k, col = m/n, pitch 136.
// a-frag for m16 tile at column base m0; b-frag for n8 tile at base n0.
#define LOAD_AFRAG(a, As, kr, m0, ms)              \
    do {                                           \
        (a)[0] = As[(kr)    ][(m0) + (ms)    ];    \
        (a)[1] = As[(kr)    ][(m0) + (ms) + 8];    \
        (a)[2] = As[(kr) + 4][(m0) + (ms)    ];    \
        (a)[3] = As[(kr) + 4][(m0) + (ms) + 8];    \
    } while (0)
#define LOAD_BFRAG(b, Bs, kr, n0, ms)              \
    do {                                           \
        (b)[0] = Bs[(kr)    ][(n0) + (ms)];        \
        (b)[1] = Bs[(kr) + 4][(n0) + (ms)];        \
    } while (0)

// ---------------------------------------------------------------------------
// Generic 128x128 tf32 GEMM, row-major A(MxK) * B(KxN) -> C(MxN), K%16==0.
// MODE 0: A plain. MODE 1: A rows = virtual concat(memory, input_) over seq.
// 256 threads = 8 warps in 2(m) x 4(n); warp tile 64x32 = 4x4 m16n8 tiles.
// ---------------------------------------------------------------------------
template <int MODE>
__global__ void __launch_bounds__(256) gemm_tf32(
    const float* __restrict__ A, const float* __restrict__ A2,
    const float* __restrict__ B, float* __restrict__ C,
    int M, int N, int K)
{
    __shared__ float As[16][136];
    __shared__ float Bs[16][136];
    const int tid  = threadIdx.x;
    const int lane = tid & 31;
    const int w    = tid >> 5;
    const int wm   = (w >> 2) * 64;
    const int wn   = (w & 3) * 32;
    const int bm   = blockIdx.y * 128;
    const int bn   = blockIdx.x * 128;

    // A tile loader: 128 rows x 16 k; thread -> row (tid&127), k-quad (tid>>7)*8
    const int ar = tid & 127;
    const int ak = (tid >> 7) * 8;
    const float* arow;
    if (MODE == 0) {
        arow = A + (size_t)(bm + ar) * K;
    } else {
        int row = bm + ar;
        int b   = row / TT;
        int r   = row - b * TT;
        arow = (r < PSQ) ? A  + (size_t)(b * PSQ + r)         * K
                         : A2 + (size_t)(b * CSQ + (r - PSQ)) * K;
    }
    // B tile loader: 16 k x 128 n; thread -> k row (tid>>4), 8 cols (tid&15)*8
    const int br = tid >> 4;
    const int bc = (tid & 15) * 8;
    const float* bp = B + (size_t)br * N + bn + bc;

    float acc[4][4][4] = {};

    for (int k0 = 0; k0 < K; k0 += 16) {
        float4 av0 = *(const float4*)(arow + k0 + ak);
        float4 av1 = *(const float4*)(arow + k0 + ak + 4);
        float4 bv0 = *(const float4*)(bp + (size_t)k0 * N);
        float4 bv1 = *(const float4*)(bp + (size_t)k0 * N + 4);
        __syncthreads();
        As[ak + 0][ar] = tf32r(av0.x);  As[ak + 1][ar] = tf32r(av0.y);
        As[ak + 2][ar] = tf32r(av0.z);  As[ak + 3][ar] = tf32r(av0.w);
        As[ak + 4][ar] = tf32r(av1.x);  As[ak + 5][ar] = tf32r(av1.y);
        As[ak + 6][ar] = tf32r(av1.z);  As[ak + 7][ar] = tf32r(av1.w);
        Bs[br][bc + 0] = tf32r(bv0.x);  Bs[br][bc + 1] = tf32r(bv0.y);
        Bs[br][bc + 2] = tf32r(bv0.z);  Bs[br][bc + 3] = tf32r(bv0.w);
        Bs[br][bc + 4] = tf32r(bv1.x);  Bs[br][bc + 5] = tf32r(bv1.y);
        Bs[br][bc + 6] = tf32r(bv1.z);  Bs[br][bc + 7] = tf32r(bv1.w);
        __syncthreads();
#pragma unroll
        for (int kk = 0; kk < 16; kk += 8) {
            const int kr = kk + (lane & 3);
            const int ms = lane >> 2;
            float a[4][4], b[4][2];
#pragma unroll
            for (int t = 0; t < 4; t++) {
                LOAD_AFRAG(a[t], As, kr, wm + t * 16, ms);
                LOAD_BFRAG(b[t], Bs, kr, wn + t * 8,  ms);
            }
#pragma unroll
            for (int mt = 0; mt < 4; mt++)
#pragma unroll
                for (int nt = 0; nt < 4; nt++)
                    mma8(acc[mt][nt], a[mt], b[nt]);
        }
    }

#pragma unroll
    for (int mt = 0; mt < 4; mt++) {
        int r0 = bm + wm + mt * 16 + (lane >> 2);
#pragma unroll
        for (int nt = 0; nt < 4; nt++) {
            int c0 = bn + wn + nt * 8 + (lane & 3) * 2;
            *(float2*)&C[(size_t)r0 * N + c0]       = make_float2(acc[mt][nt][0], acc[mt][nt][1]);
            *(float2*)&C[(size_t)(r0 + 8) * N + c0] = make_float2(acc[mt][nt][2], acc[mt][nt][3]);
        }
    }
}

// ---------------------------------------------------------------------------
// P[h][L][jj] = sum_d (q[L,h,d]+v[h,d]) * p[jj,h,d]   (NT, K=64)
// Block 128x128 per head; same warp layout as gemm_tf32.
// ---------------------------------------------------------------------------
__global__ void __launch_bounds__(256) pos_gemm_tf32(
    const float* __restrict__ q, const float* __restrict__ p,
    const float* __restrict__ vb, float* __restrict__ P)
{
    __shared__ float As[16][136];
    __shared__ float Bs[16][136];
    const int tid  = threadIdx.x;
    const int lane = tid & 31;
    const int w    = tid >> 5;
    const int wm   = (w >> 2) * 64;
    const int wn   = (w & 3) * 32;
    const int h    = blockIdx.z;
    const int L0   = blockIdx.y * 128;
    const int j0   = blockIdx.x * 128;

    const int ar = tid & 127;
    const int ak = (tid >> 7) * 8;
    const float* arow = q  + (size_t)(L0 + ar) * HD + h * HDIM + ak;
    const float* vrow = vb + h * HDIM + ak;
    const float* brow = p  + (size_t)(j0 + ar) * HD + h * HDIM + ak;  // same row/quad map

    float acc[4][4][4] = {};

#pragma unroll
    for (int k0 = 0; k0 < HDIM; k0 += 16) {
        float4 av0 = *(const float4*)(arow + k0);
        float4 av1 = *(const float4*)(arow + k0 + 4);
        float4 vv0 = *(const float4*)(vrow + k0);
        float4 vv1 = *(const float4*)(vrow + k0 + 4);
        float4 bv0 = *(const float4*)(brow + k0);
        float4 bv1 = *(const float4*)(brow + k0 + 4);
        __syncthreads();
        As[ak + 0][ar] = tf32r(av0.x + vv0.x);  As[ak + 1][ar] = tf32r(av0.y + vv0.y);
        As[ak + 2][ar] = tf32r(av0.z + vv0.z);  As[ak + 3][ar] = tf32r(av0.w + vv0.w);
        As[ak + 4][ar] = tf32r(av1.x + vv1.x);  As[ak + 5][ar] = tf32r(av1.y + vv1.y);
        As[ak + 6][ar] = tf32r(av1.z + vv1.z);  As[ak + 7][ar] = tf32r(av1.w + vv1.w);
        Bs[ak + 0][ar] = tf32r(bv0.x);  Bs[ak + 1][ar] = tf32r(bv0.y);
        Bs[ak + 2][ar] = tf32r(bv0.z);  Bs[ak + 3][ar] = tf32r(bv0.w);
        Bs[ak + 4][ar] = tf32r(bv1.x);  Bs[ak + 5][ar] = tf32r(bv1.y);
        Bs[ak + 6][ar] = tf32r(bv1.z);  Bs[ak + 7][ar] = tf32r(bv1.w);
        __syncthreads();
#pragma unroll
        for (int kk = 0; kk < 16; kk += 8) {
            const int kr = kk + (lane & 3);
            const int ms = lane >> 2;
            float a[4][4], b[4][2];
#pragma unroll
            for (int t = 0; t < 4; t++) {
                LOAD_AFRAG(a[t], As, kr, wm + t * 16, ms);
                LOAD_BFRAG(b[t], Bs, kr, wn + t * 8,  ms);
            }
#pragma unroll
            for (int mt = 0; mt < 4; mt++)
#pragma unroll
                for (int nt = 0; nt < 4; nt++)
                    mma8(acc[mt][nt], a[mt], b[nt]);
        }
    }

#pragma unroll
    for (int mt = 0; mt < 4; mt++) {
        int r0 = L0 + wm + mt * 16 + (lane >> 2);
#pragma unroll
        for (int nt = 0; nt < 4; nt++) {
            int c0 = j0 + wn + nt * 8 + (lane & 3) * 2;
            float* o = P + ((size_t)h * LQG + r0) * TT + c0;
            *(float2*)o              = make_float2(acc[mt][nt][0], acc[mt][nt][1]);
            *(float2*)(o + 8 * TT)   = make_float2(acc[mt][nt][2], acc[mt][nt][3]);
        }
    }
}

// ---------------------------------------------------------------------------
// rel_shift gather: pos(b,i,j) with L = b*CS+i
// ---------------------------------------------------------------------------
__device__ __forceinline__ float pos_val(const float* __restrict__ Pm,
                                         int h, int L, int jj)
{
    int s  = jj + LQG - L;
    int n  = (s > TT) + (s > 2 * TT + 1);
    int jp = s - n * (TT + 1);
    int Lp = L + n;
    float pos = 0.f;
    if (jp > 0 && Lp < LQG)
        pos = Pm[((size_t)h * LQG + Lp) * TT + (jp - 1)];
    return pos;
}

// ---------------------------------------------------------------------------
// Scores: S[b,h,i,j] = (q+u)·k + rel_shift(P), masked. Block 128x128, K=64.
// ---------------------------------------------------------------------------
__global__ void __launch_bounds__(256) score_gemm_tf32(
    const float* __restrict__ q, const float* __restrict__ kv,
    const float* __restrict__ ub, const float* __restrict__ Pm,
    float* __restrict__ S)
{
    __shared__ float As[16][136];
    __shared__ float Bs[16][136];
    const int tid  = threadIdx.x;
    const int lane = tid & 31;
    const int w    = tid >> 5;
    const int wm   = (w >> 2) * 64;
    const int wn   = (w & 3) * 32;
    const int bh   = blockIdx.z;
    const int b    = bh >> 4;
    const int h    = bh & 15;
    const int i0   = blockIdx.y * 128;
    const int j0   = blockIdx.x * 128;

    const int ar = tid & 127;
    const int ak = (tid >> 7) * 8;
    const float* arow = q  + (size_t)(b * CSQ + i0 + ar) * HD + h * HDIM + ak;
    const float* urow = ub + h * HDIM + ak;
    const float* brow = kv + ((size_t)b * TT + j0 + ar) * (2 * HD) + h * HDIM + ak;

    float acc[4][4][4] = {};

#pragma unroll
    for (int k0 = 0; k0 < HDIM; k0 += 16) {
        float4 av0 = *(const float4*)(arow + k0);
        float4 av1 = *(const float4*)(arow + k0 + 4);
        float4 uv0 = *(const float4*)(urow + k0);
        float4 uv1 = *(const float4*)(urow + k0 + 4);
        float4 bv0 = *(const float4*)(brow + k0);
        float4 bv1 = *(const float4*)(brow + k0 + 4);
        __syncthreads();
        As[ak + 0][ar] = tf32r(av0.x + uv0.x);  As[ak + 1][ar] = tf32r(av0.y + uv0.y);
        As[ak + 2][ar] = tf32r(av0.z + uv0.z);  As[ak + 3][ar] = tf32r(av0.w + uv0.w);
        As[ak + 4][ar] = tf32r(av1.x + uv1.x);  As[ak + 5][ar] = tf32r(av1.y + uv1.y);
        As[ak + 6][ar] = tf32r(av1.z + uv1.z);  As[ak + 7][ar] = tf32r(av1.w + uv1.w);
        Bs[ak + 0][ar] = tf32r(bv0.x);  Bs[ak + 1][ar] = tf32r(bv0.y);
        Bs[ak + 2][ar] = tf32r(bv0.z);  Bs[ak + 3][ar] = tf32r(bv0.w);
        Bs[ak + 4][ar] = tf32r(bv1.x);  Bs[ak + 5][ar] = tf32r(bv1.y);
        Bs[ak + 6][ar] = tf32r(bv1.z);  Bs[ak + 7][ar] = tf32r(bv1.w);
        __syncthreads();
#pragma unroll
        for (int kk = 0; kk < 16; kk += 8) {
            const int kr = kk + (lane & 3);
            const int ms = lane >> 2;
            float a[4][4], bq[4][2];
#pragma unroll
            for (int t = 0; t < 4; t++) {
                LOAD_AFRAG(a[t],  As, kr, wm + t * 16, ms);
                LOAD_BFRAG(bq[t], Bs, kr, wn + t * 8,  ms);
            }
#pragma unroll
            for (int mt = 0; mt < 4; mt++)
#pragma unroll
                for (int nt = 0; nt < 4; nt++)
                    mma8(acc[mt][nt], a[mt], bq[nt]);
        }
    }

#pragma unroll
    for (int mt = 0; mt < 4; mt++) {
        int ii_base = i0 + wm + mt * 16 + (lane >> 2);
#pragma unroll
        for (int nt = 0; nt < 4; nt++) {
            int jj0 = j0 + wn + nt * 8 + (lane & 3) * 2;
#pragma unroll
            for (int rr = 0; rr < 2; rr++) {
                int ii = ii_base + rr * 8;
                int L  = b * CSQ + ii;
                float v0, v1;
                if (jj0 > ii + PSQ)       v0 = -1e30f;
                else                      v0 = acc[mt][nt][rr * 2 + 0] + pos_val(Pm, h, L, jj0);
                if (jj0 + 1 > ii + PSQ)   v1 = -1e30f;
                else                      v1 = acc[mt][nt][rr * 2 + 1] + pos_val(Pm, h, L, jj0 + 1);
                float* so = S + ((size_t)(b * NH + h) * CSQ + ii) * TT + jj0;
                *(float2*)so = make_float2(v0, v1);
            }
        }
    }
}

// ---------------------------------------------------------------------------
// Row softmax over j (T=2048) of SCALE*score, in place. 1 block per row.
// ---------------------------------------------------------------------------
__global__ void __launch_bounds__(256) softmax_k(float* __restrict__ S)
{
    const int t = threadIdx.x;
    float* x = S + (size_t)blockIdx.x * TT;
    float v[8];
    float m = -3.0e38f;
#pragma unroll
    for (int r = 0; r < 8; r++) {
        v[r] = x[t + 256 * r];
        m = fmaxf(m, v[r]);
    }
#pragma unroll
    for (int o = 16; o > 0; o >>= 1)
        m = fmaxf(m, __shfl_xor_sync(0xffffffffu, m, o));
    __shared__ float red[8];
    if ((t & 31) == 0) red[t >> 5] = m;
    __syncthreads();
    float bm = red[0];
#pragma unroll
    for (int w = 1; w < 8; w++) bm = fmaxf(bm, red[w]);

    float s = 0.f;
#pragma unroll
    for (int r = 0; r < 8; r++) {
        v[r] = __expf((v[r] - bm) * SCALE);
        s += v[r];
    }
#pragma unroll
    for (int o = 16; o > 0; o >>= 1)
        s += __shfl_xor_sync(0xffffffffu, s, o);
    __syncthreads();
    if ((t & 31) == 0) red[t >> 5] = s;
    __syncthreads();
    float tot = 0.f;
#pragma unroll
    for (int w = 0; w < 8; w++) tot += red[w];
    float inv = 1.0f / tot;
#pragma unroll
    for (int r = 0; r < 8; r++)
        x[t + 256 * r] = v[r] * inv;
}

// ---------------------------------------------------------------------------
// ao[b,i,h,:] = sum_j S[b,h,i,j] * v[b,j,h,:]
// Block 128x64; 8 warps in 4(m) x 2(n); warp 32x32 = 2x4 m16n8 tiles.
// K truncated by causality: rows [i0, i0+127] see zero prob for j>=i0+128+PS.
// ---------------------------------------------------------------------------
__global__ void __launch_bounds__(256) awv_gemm_tf32(
    const float* __restrict__ S, const float* __restrict__ kv,
    float* __restrict__ ao)
{
    __shared__ float As[16][136];
    __shared__ float Bs[16][72];
    const int tid  = threadIdx.x;
    const int lane = tid & 31;
    const int w    = tid >> 5;
    const int wm   = (w >> 1) * 32;
    const int wn   = (w & 1) * 32;
    const int bh   = blockIdx.z;
    const int b    = bh >> 4;
    const int h    = bh & 15;
    const int i0   = blockIdx.y * 128;

    const int ar = tid & 127;
    const int ak = (tid >> 7) * 8;
    const float* arow = S + ((size_t)(b * NH + h) * CSQ + i0 + ar) * TT + ak;
    const int bkr = tid >> 4;          // k row 0..15
    const int bcc = (tid & 15) * 4;    // col quad
    const float* bbase = kv + ((size_t)b * TT + bkr) * (2 * HD) + HD + h * HDIM + bcc;

    float acc[2][4][4] = {};
    const int Kef = min(TT, i0 + 128 + PSQ);

    for (int k0 = 0; k0 < Kef; k0 += 16) {
        float4 av0 = *(const float4*)(arow + k0);
        float4 av1 = *(const float4*)(arow + k0 + 4);
        float4 bv  = *(const float4*)(bbase + (size_t)k0 * (2 * HD));
        __syncthreads();
        As[ak + 0][ar] = tf32r(av0.x);  As[ak + 1][ar] = tf32r(av0.y);
        As[ak + 2][ar] = tf32r(av0.z);  As[ak + 3][ar] = tf32r(av0.w);
        As[ak + 4][ar] = tf32r(av1.x);  As[ak + 5][ar] = tf32r(av1.y);
        As[ak + 6][ar] = tf32r(av1.z);  As[ak + 7][ar] = tf32r(av1.w);
        Bs[bkr][bcc + 0] = tf32r(bv.x);
        Bs[bkr][bcc + 1] = tf32r(bv.y);
        Bs[bkr][bcc + 2] = tf32r(bv.z);
        Bs[bkr][bcc + 3] = tf32r(bv.w);
        __syncthreads();
#pragma unroll
        for (int kk = 0; kk < 16; kk += 8) {
            const int kr = kk + (lane & 3);
            const int ms = lane >> 2;
            float a[2][4], bq[4][2];
#pragma unroll
            for (int t = 0; t < 2; t++)
                LOAD_AFRAG(a[t], As, kr, wm + t * 16, ms);
#pragma unroll
            for (int t = 0; t < 4; t++)
                LOAD_BFRAG(bq[t], Bs, kr, wn + t * 8, ms);
#pragma unroll
            for (int mt = 0; mt < 2; mt++)
#pragma unroll
                for (int nt = 0; nt < 4; nt++)
                    mma8(acc[mt][nt], a[mt], bq[nt]);
        }
    }

#pragma unroll
    for (int mt = 0; mt < 2; mt++) {
        int r0 = i0 + wm + mt * 16 + (lane >> 2);
#pragma unroll
        for (int nt = 0; nt < 4; nt++) {
            int c0 = wn + nt * 8 + (lane & 3) * 2;
            float* o = ao + (size_t)(b * CSQ + r0) * HD + h * HDIM + c0;
            *(float2*)o            = make_float2(acc[mt][nt][0], acc[mt][nt][1]);
            *(float2*)(o + 8 * HD) = make_float2(acc[mt][nt][2], acc[mt][nt][3]);
        }
    }
}

// ---------------------------------------------------------------------------
// Launch: 8 kernels, default stream, graph-capturable.
// Inputs: input_, pos_embs, memory, u, v, W_kv, W_q, W_p, W_out, mask(unused).
// ---------------------------------------------------------------------------
extern "C" void kernel_launch(void* const* d_in, const int* in_sizes, int n_in,
                              void* d_out, int out_size)
{
    const float* input_ = (const float*)d_in[0];
    const float* pos    = (const float*)d_in[1];
    const float* memory = (const float*)d_in[2];
    const float* u      = (const float*)d_in[3];
    const float* v      = (const float*)d_in[4];
    const float* W_kv   = (const float*)d_in[5];
    const float* W_q    = (const float*)d_in[6];
    const float* W_p    = (const float*)d_in[7];
    const float* W_out  = (const float*)d_in[8];
    float* out = (float*)d_out;

    float *qb, *kvb, *pb, *Pb, *Sb, *aob;
    cudaGetSymbolAddress((void**)&qb,  g_q);
    cudaGetSymbolAddress((void**)&kvb, g_kv);
    cudaGetSymbolAddress((void**)&pb,  g_p);
    cudaGetSymbolAddress((void**)&Pb,  g_P);
    cudaGetSymbolAddress((void**)&Sb,  g_S);
    cudaGetSymbolAddress((void**)&aob, g_ao);

    dim3 thr(256);

    // q = input_ @ W_q                      (4096 x 1024 x 1024)
    gemm_tf32<0><<<dim3(HD / 128, LQG / 128), thr>>>(input_, nullptr, W_q, qb, LQG, HD, DIN);
    // kv = concat(memory, input_) @ W_kv    (8192 x 2048 x 1024)
    gemm_tf32<1><<<dim3(2 * HD / 128, (BSZ * TT) / 128), thr>>>(memory, input_, W_kv, kvb, BSZ * TT, 2 * HD, DIN);
    // p = pos_embs @ W_p                    (2048 x 1024 x 1024)
    gemm_tf32<0><<<dim3(HD / 128, TT / 128), thr>>>(pos, nullptr, W_p, pb, TT, HD, DIN);
    // P[h] = (q + v) @ p^T per head         (16 x 4096 x 2048 x 64)
    pos_gemm_tf32<<<dim3(TT / 128, LQG / 128, NH), thr>>>(qb, pb, v, Pb);
    // scores + rel-shift gather + mask
    score_gemm_tf32<<<dim3(TT / 128, CSQ / 128, BSZ * NH), thr>>>(qb, kvb, u, Pb, Sb);
    // softmax
    softmax_k<<<BSZ * NH * CSQ, thr>>>(Sb);
    // attn @ V
    awv_gemm_tf32<<<dim3(1, CSQ / 128, BSZ * NH), thr>>>(Sb, kvb, aob);
    // out = ao @ W_out                      (4096 x 1024 x 1024)
    gemm_tf32<0><<<dim3(DIN / 128, LQG / 128), thr>>>(aob, nullptr, W_out, out, LQG, DIN, HD);
}